// round 9
// baseline (speedup 1.0000x reference)
#include <cuda_runtime.h>

#define C1 1.125f
#define C2 (-1.0f/24.0f)

__device__ __forceinline__ float4 ld4(const float* p) {
    return *reinterpret_cast<const float4*>(p);
}
__device__ __forceinline__ void st4(float* p, float4 v) {
    *reinterpret_cast<float4*>(p) = v;
}
// L2 evict_last via cache-policy register (sm_80+ encoding; works on sm_103a)
__device__ __forceinline__ unsigned long long mk_evict_last_policy() {
    unsigned long long pol;
    asm("createpolicy.fractional.L2::evict_last.b64 %0, 1.0;" : "=l"(pol));
    return pol;
}
__device__ __forceinline__ float4 ld4_el(const float* p, unsigned long long pol) {
    float4 v;
    asm("ld.global.L2::cache_hint.v4.f32 {%0,%1,%2,%3}, [%4], %5;"
        : "=f"(v.x), "=f"(v.y), "=f"(v.z), "=f"(v.w) : "l"(p), "l"(pol));
    return v;
}
__device__ __forceinline__ void st4_el(float* p, float4 v, unsigned long long pol) {
    asm volatile("st.global.L2::cache_hint.v4.f32 [%0], {%1,%2,%3,%4}, %5;"
        :: "l"(p), "f"(v.x), "f"(v.y), "f"(v.z), "f"(v.w), "l"(pol) : "memory");
}
__device__ __forceinline__ float4 f4zero() { return make_float4(0.f,0.f,0.f,0.f); }

// ---------------- Kernel 1: update_E (vectorized x4) ----------------
__global__ void __launch_bounds__(256) upd_E(
    const float* __restrict__ ca, const float* __restrict__ cb,
    const float* __restrict__ Ey, const float* __restrict__ Hx,
    const float* __restrict__ Hz,
    const float* __restrict__ mHxz, const float* __restrict__ mHzx,
    const float* __restrict__ ky, const float* __restrict__ ay,
    const float* __restrict__ by,
    const float* __restrict__ kx, const float* __restrict__ ax,
    const float* __restrict__ bx,
    const float* __restrict__ prdy, const float* __restrict__ prdx,
    float* __restrict__ outEy, float* __restrict__ outmHxz,
    float* __restrict__ outmHzx,
    int NY, int NX, unsigned int bshift, unsigned int bmask)
{
    // batch varies FASTEST in block order (shift/mask, pow2 B)
    unsigned int b    = blockIdx.x & bmask;
    unsigned int bxid = blockIdx.x >> bshift;
    int x4 = (bxid * blockDim.x + threadIdx.x) * 4;
    int y  = blockIdx.y * blockDim.y + threadIdx.y;
    if (x4 >= NX || y >= NY) return;

    const unsigned long long pol = mk_evict_last_policy();
    const float rdx = *prdx;
    const float rdy = *prdy;

    size_t plane = (size_t)NY * NX;
    size_t base  = (size_t)b * plane + (size_t)y * NX + x4;

    // x-direction neighbors of Hz (zero-padded); center load protects the line
    float4 c = ld4_el(Hz + base, pol);
    float4 p = (x4 >= 4)      ? ld4(Hz + base - 4) : f4zero();
    float4 n = (x4 + 4 < NX)  ? ld4(Hz + base + 4) : f4zero();

    float4 dHzdx;
    dHzdx.x = (C1 * (c.x - p.w) + C2 * (c.y - p.z)) * rdx;
    dHzdx.y = (C1 * (c.y - c.x) + C2 * (c.z - p.w)) * rdx;
    dHzdx.z = (C1 * (c.z - c.y) + C2 * (c.w - c.x)) * rdx;
    dHzdx.w = (C1 * (c.w - c.z) + C2 * (n.x - c.y)) * rdx;

    // y-direction neighbors of Hx (zero-padded); center row protects the line
    float4 r0  = ld4_el(Hx + base, pol);
    float4 rm1 = (y >= 1)     ? ld4(Hx + base - (size_t)NX)     : f4zero();
    float4 rm2 = (y >= 2)     ? ld4(Hx + base - 2*(size_t)NX)   : f4zero();
    float4 rp1 = (y + 1 < NY) ? ld4(Hx + base + (size_t)NX)     : f4zero();

    float4 dHxdz;
    dHxdz.x = (C1 * (r0.x - rm1.x) + C2 * (rp1.x - rm2.x)) * rdy;
    dHxdz.y = (C1 * (r0.y - rm1.y) + C2 * (rp1.y - rm2.y)) * rdy;
    dHxdz.z = (C1 * (r0.z - rm1.z) + C2 * (rp1.z - rm2.z)) * rdy;
    dHxdz.w = (C1 * (r0.w - rm1.w) + C2 * (rp1.w - rm2.w)) * rdy;

    float4 bx4 = ld4(bx + x4);
    float4 ax4 = ld4(ax + x4);
    float4 kx4 = ld4(kx + x4);
    float  byv = by[y], ayv = ay[y];
    float  rky = 1.0f / ky[y];

    float4 mzx = ld4(mHzx + base);
    mzx.x = bx4.x * mzx.x + ax4.x * dHzdx.x;
    mzx.y = bx4.y * mzx.y + ax4.y * dHzdx.y;
    mzx.z = bx4.z * mzx.z + ax4.z * dHzdx.z;
    mzx.w = bx4.w * mzx.w + ax4.w * dHzdx.w;

    float4 mxz = ld4(mHxz + base);
    mxz.x = byv * mxz.x + ayv * dHxdz.x;
    mxz.y = byv * mxz.y + ayv * dHxdz.y;
    mxz.z = byv * mxz.z + ayv * dHxdz.z;
    mxz.w = byv * mxz.w + ayv * dHxdz.w;

    size_t cidx = (size_t)y * NX + x4;
    float4 ca4 = ld4(ca + cidx);
    float4 cb4 = ld4(cb + cidx);
    float4 ey  = ld4(Ey + base);

    ey.x = ca4.x * ey.x + cb4.x * ((dHzdx.x / kx4.x + mzx.x) - (dHxdz.x * rky + mxz.x));
    ey.y = ca4.y * ey.y + cb4.y * ((dHzdx.y / kx4.y + mzx.y) - (dHxdz.y * rky + mxz.y));
    ey.z = ca4.z * ey.z + cb4.z * ((dHzdx.z / kx4.z + mzx.z) - (dHxdz.z * rky + mxz.z));
    ey.w = ca4.w * ey.w + cb4.w * ((dHzdx.w / kx4.w + mzx.w) - (dHxdz.w * rky + mxz.w));

    st4_el(outEy + base, ey, pol);   // protected: upd_H re-reads this
    st4(outmHzx + base, mzx);
    st4(outmHxz + base, mxz);
}

// ---------------- Kernel 2: update_H (vectorized x4) ----------------
__global__ void __launch_bounds__(256) upd_H(
    const float* __restrict__ cq,
    const float* __restrict__ EyNew,
    const float* __restrict__ Hx, const float* __restrict__ Hz,
    const float* __restrict__ mEyx, const float* __restrict__ mEyz,
    const float* __restrict__ kyh, const float* __restrict__ ayh,
    const float* __restrict__ byh,
    const float* __restrict__ kxh, const float* __restrict__ axh,
    const float* __restrict__ bxh,
    const float* __restrict__ prdy, const float* __restrict__ prdx,
    float* __restrict__ outHx, float* __restrict__ outHz,
    float* __restrict__ outmEyx, float* __restrict__ outmEyz,
    int NY, int NX, unsigned int bshift, unsigned int bmask)
{
    unsigned int b    = blockIdx.x & bmask;
    unsigned int bxid = blockIdx.x >> bshift;
    int x4 = (bxid * blockDim.x + threadIdx.x) * 4;
    int y  = blockIdx.y * blockDim.y + threadIdx.y;
    if (x4 >= NX || y >= NY) return;

    const float rdx = *prdx;
    const float rdy = *prdy;

    size_t plane = (size_t)NY * NX;
    size_t base  = (size_t)b * plane + (size_t)y * NX + x4;

    // x-direction neighbors of new Ey
    float4 c = ld4(EyNew + base);
    float4 p = (x4 >= 4)     ? ld4(EyNew + base - 4) : f4zero();
    float4 n = (x4 + 4 < NX) ? ld4(EyNew + base + 4) : f4zero();

    float4 dEydx;
    dEydx.x = (C1 * (c.y - c.x) + C2 * (c.z - p.w)) * rdx;
    dEydx.y = (C1 * (c.z - c.y) + C2 * (c.w - c.x)) * rdx;
    dEydx.z = (C1 * (c.w - c.z) + C2 * (n.x - c.y)) * rdx;
    dEydx.w = (C1 * (n.x - c.w) + C2 * (n.y - c.z)) * rdx;

    // y-direction neighbors of new Ey
    float4 rm1 = (y >= 1)     ? ld4(EyNew + base - (size_t)NX)   : f4zero();
    float4 rp1 = (y + 1 < NY) ? ld4(EyNew + base + (size_t)NX)   : f4zero();
    float4 rp2 = (y + 2 < NY) ? ld4(EyNew + base + 2*(size_t)NX) : f4zero();

    float4 dEydz;
    dEydz.x = (C1 * (rp1.x - c.x) + C2 * (rp2.x - rm1.x)) * rdy;
    dEydz.y = (C1 * (rp1.y - c.y) + C2 * (rp2.y - rm1.y)) * rdy;
    dEydz.z = (C1 * (rp1.z - c.z) + C2 * (rp2.z - rm1.z)) * rdy;
    dEydz.w = (C1 * (rp1.w - c.w) + C2 * (rp2.w - rm1.w)) * rdy;

    float4 bxh4 = ld4(bxh + x4);
    float4 axh4 = ld4(axh + x4);
    float4 kxh4 = ld4(kxh + x4);
    float  byhv = byh[y], ayhv = ayh[y];
    float  rkyh = 1.0f / kyh[y];

    float4 mez = ld4(mEyz + base);
    mez.x = byhv * mez.x + ayhv * dEydz.x;
    mez.y = byhv * mez.y + ayhv * dEydz.y;
    mez.z = byhv * mez.z + ayhv * dEydz.z;
    mez.w = byhv * mez.w + ayhv * dEydz.w;

    float4 mex = ld4(mEyx + base);
    mex.x = bxh4.x * mex.x + axh4.x * dEydx.x;
    mex.y = bxh4.y * mex.y + axh4.y * dEydx.y;
    mex.z = bxh4.z * mex.z + axh4.z * dEydx.z;
    mex.w = bxh4.w * mex.w + axh4.w * dEydx.w;

    size_t cidx = (size_t)y * NX + x4;
    float4 cq4 = ld4(cq + cidx);

    float4 hx = ld4(Hx + base);
    hx.x = hx.x - cq4.x * (dEydz.x * rkyh + mez.x);
    hx.y = hx.y - cq4.y * (dEydz.y * rkyh + mez.y);
    hx.z = hx.z - cq4.z * (dEydz.z * rkyh + mez.z);
    hx.w = hx.w - cq4.w * (dEydz.w * rkyh + mez.w);

    float4 hz = ld4(Hz + base);
    hz.x = hz.x + cq4.x * (dEydx.x / kxh4.x + mex.x);
    hz.y = hz.y + cq4.y * (dEydx.y / kxh4.y + mex.y);
    hz.z = hz.z + cq4.z * (dEydx.z / kxh4.z + mex.z);
    hz.w = hz.w + cq4.w * (dEydx.w / kxh4.w + mex.w);

    st4(outHx   + base, hx);
    st4(outHz   + base, hz);
    st4(outmEyz + base, mez);
    st4(outmEyx + base, mex);
}

extern "C" void kernel_launch(void* const* d_in, const int* in_sizes, int n_in,
                              void* d_out, int out_size)
{
    const float* ca    = (const float*)d_in[0];
    const float* cb    = (const float*)d_in[1];
    const float* cq    = (const float*)d_in[2];
    const float* Ey    = (const float*)d_in[3];
    const float* Hx    = (const float*)d_in[4];
    const float* Hz    = (const float*)d_in[5];
    const float* mHxz  = (const float*)d_in[6];
    const float* mHzx  = (const float*)d_in[7];
    const float* mEyx  = (const float*)d_in[8];
    const float* mEyz  = (const float*)d_in[9];
    const float* ky    = (const float*)d_in[10];
    const float* kyh   = (const float*)d_in[11];
    const float* ay    = (const float*)d_in[12];
    const float* ayh   = (const float*)d_in[13];
    const float* by    = (const float*)d_in[14];
    const float* byh   = (const float*)d_in[15];
    const float* kx    = (const float*)d_in[16];
    const float* kxh   = (const float*)d_in[17];
    const float* ax    = (const float*)d_in[18];
    const float* axh   = (const float*)d_in[19];
    const float* bx    = (const float*)d_in[20];
    const float* bxh   = (const float*)d_in[21];
    const float* prdy  = (const float*)d_in[22];
    const float* prdx  = (const float*)d_in[23];

    int NY = in_sizes[10];
    int NX = in_sizes[16];
    int B  = in_sizes[3] / (NY * NX);

    unsigned int bshift = 0;
    while ((1u << bshift) < (unsigned)B) bshift++;
    unsigned int Bp2   = 1u << bshift;
    unsigned int bmask = Bp2 - 1;

    size_t plane = (size_t)NY * NX;
    size_t field = (size_t)B * plane;

    float* out = (float*)d_out;
    float* oEy   = out + 0 * field;
    float* oHx   = out + 1 * field;
    float* oHz   = out + 2 * field;
    float* omHxz = out + 3 * field;
    float* omHzx = out + 4 * field;
    float* omEyx = out + 5 * field;
    float* omEyz = out + 6 * field;

    dim3 block(64, 4, 1);
    int nx4 = NX / 4;                       // 512
    int gx  = (nx4 + 63) / 64;              // 8
    dim3 grid(gx * Bp2, (NY + 3) / 4, 1);

    upd_E<<<grid, block>>>(ca, cb, Ey, Hx, Hz, mHxz, mHzx,
                           ky, ay, by, kx, ax, bx, prdy, prdx,
                           oEy, omHxz, omHzx, NY, NX, bshift, bmask);

    upd_H<<<grid, block>>>(cq, oEy, Hx, Hz, mEyx, mEyz,
                           kyh, ayh, byh, kxh, axh, bxh, prdy, prdx,
                           oHx, oHz, omEyx, omEyz, NY, NX, bshift, bmask);
}

// round 10
// speedup vs baseline: 1.0412x; 1.0412x over previous
#include <cuda_runtime.h>

#define C1 1.125f
#define C2 (-1.0f/24.0f)

__device__ __forceinline__ float4 ld4(const float* p) {
    return *reinterpret_cast<const float4*>(p);
}
__device__ __forceinline__ void st4(float* p, float4 v) {
    *reinterpret_cast<float4*>(p) = v;
}
__device__ __forceinline__ float4 f4zero() { return make_float4(0.f,0.f,0.f,0.f); }

// elementwise helpers
__device__ __forceinline__ float4 stencil4(float4 a, float4 b, float4 c, float4 d, float s) {
    // (C1*(a-b) + C2*(c-d)) * s
    float4 r;
    r.x = (C1 * (a.x - b.x) + C2 * (c.x - d.x)) * s;
    r.y = (C1 * (a.y - b.y) + C2 * (c.y - d.y)) * s;
    r.z = (C1 * (a.z - b.z) + C2 * (c.z - d.z)) * s;
    r.w = (C1 * (a.w - b.w) + C2 * (c.w - d.w)) * s;
    return r;
}

// x-stencil for update_E: lanewise needs x-2..x+1  (c=center f4, p=prev f4, n=next f4)
__device__ __forceinline__ float4 xderiv_E(float4 c, float4 p, float4 n, float s) {
    float4 r;
    r.x = (C1 * (c.x - p.w) + C2 * (c.y - p.z)) * s;
    r.y = (C1 * (c.y - c.x) + C2 * (c.z - p.w)) * s;
    r.z = (C1 * (c.z - c.y) + C2 * (c.w - c.x)) * s;
    r.w = (C1 * (c.w - c.z) + C2 * (n.x - c.y)) * s;
    return r;
}
// x-stencil for update_H: lanewise needs x-1..x+2
__device__ __forceinline__ float4 xderiv_H(float4 c, float4 p, float4 n, float s) {
    float4 r;
    r.x = (C1 * (c.y - c.x) + C2 * (c.z - p.w)) * s;
    r.y = (C1 * (c.z - c.y) + C2 * (c.w - c.x)) * s;
    r.z = (C1 * (c.w - c.z) + C2 * (n.x - c.y)) * s;
    r.w = (C1 * (n.x - c.w) + C2 * (n.y - c.z)) * s;
    return r;
}

// ---------------- Kernel 1: update_E (x4 vector, 2 y-rows/thread) ----------------
__global__ void __launch_bounds__(256) upd_E(
    const float* __restrict__ ca, const float* __restrict__ cb,
    const float* __restrict__ Ey, const float* __restrict__ Hx,
    const float* __restrict__ Hz,
    const float* __restrict__ mHxz, const float* __restrict__ mHzx,
    const float* __restrict__ ky, const float* __restrict__ ay,
    const float* __restrict__ by,
    const float* __restrict__ kx, const float* __restrict__ ax,
    const float* __restrict__ bx,
    const float* __restrict__ prdy, const float* __restrict__ prdx,
    float* __restrict__ outEy, float* __restrict__ outmHxz,
    float* __restrict__ outmHzx,
    int NY, int NX)
{
    int x4 = (blockIdx.x * blockDim.x + threadIdx.x) * 4;
    int y0 = (blockIdx.y * blockDim.y + threadIdx.y) * 2;
    int b  = blockIdx.z;
    if (x4 >= NX || y0 >= NY) return;
    int y1 = y0 + 1;                         // NY even -> y1 < NY

    const float rdx = *prdx;
    const float rdy = *prdy;

    size_t plane = (size_t)NY * NX;
    size_t base0 = (size_t)b * plane + (size_t)y0 * NX + x4;
    size_t base1 = base0 + NX;

    // ---- x-derivative of Hz for both rows ----
    float4 c0 = ld4(Hz + base0);
    float4 c1 = ld4(Hz + base1);
    float4 p0 = (x4 >= 4)     ? ld4(Hz + base0 - 4) : f4zero();
    float4 p1 = (x4 >= 4)     ? ld4(Hz + base1 - 4) : f4zero();
    float4 n0 = (x4 + 4 < NX) ? ld4(Hz + base0 + 4) : f4zero();
    float4 n1 = (x4 + 4 < NX) ? ld4(Hz + base1 + 4) : f4zero();
    float4 dHzdx0 = xderiv_E(c0, p0, n0, rdx);
    float4 dHzdx1 = xderiv_E(c1, p1, n1, rdx);

    // ---- y-derivative of Hx: rows y0-2 .. y0+2 (5 loads for 2 rows) ----
    float4 h0 = (y0 >= 2)     ? ld4(Hx + base0 - 2*(size_t)NX) : f4zero();
    float4 h1 = (y0 >= 1)     ? ld4(Hx + base0 - (size_t)NX)   : f4zero();
    float4 h2 = ld4(Hx + base0);
    float4 h3 = ld4(Hx + base1);
    float4 h4 = (y0 + 2 < NY) ? ld4(Hx + base0 + 2*(size_t)NX) : f4zero();
    float4 dHxdz0 = stencil4(h2, h1, h3, h0, rdy);   // row y0: C1*(h[y]-h[y-1])+C2*(h[y+1]-h[y-2])
    float4 dHxdz1 = stencil4(h3, h2, h4, h1, rdy);   // row y1

    // ---- x coefficients (shared by both rows) ----
    float4 bx4 = ld4(bx + x4);
    float4 ax4 = ld4(ax + x4);
    float4 kx4 = ld4(kx + x4);
    // y coefficients per row
    float by0 = by[y0], ay0 = ay[y0], rky0 = 1.0f / ky[y0];
    float by1 = by[y1], ay1 = ay[y1], rky1 = 1.0f / ky[y1];

    // ---- row y0 ----
    {
        float4 mzx = ld4(mHzx + base0);
        mzx.x = bx4.x * mzx.x + ax4.x * dHzdx0.x;
        mzx.y = bx4.y * mzx.y + ax4.y * dHzdx0.y;
        mzx.z = bx4.z * mzx.z + ax4.z * dHzdx0.z;
        mzx.w = bx4.w * mzx.w + ax4.w * dHzdx0.w;

        float4 mxz = ld4(mHxz + base0);
        mxz.x = by0 * mxz.x + ay0 * dHxdz0.x;
        mxz.y = by0 * mxz.y + ay0 * dHxdz0.y;
        mxz.z = by0 * mxz.z + ay0 * dHxdz0.z;
        mxz.w = by0 * mxz.w + ay0 * dHxdz0.w;

        size_t cidx = (size_t)y0 * NX + x4;
        float4 ca4 = ld4(ca + cidx);
        float4 cb4 = ld4(cb + cidx);
        float4 ey  = ld4(Ey + base0);

        ey.x = ca4.x * ey.x + cb4.x * ((dHzdx0.x / kx4.x + mzx.x) - (dHxdz0.x * rky0 + mxz.x));
        ey.y = ca4.y * ey.y + cb4.y * ((dHzdx0.y / kx4.y + mzx.y) - (dHxdz0.y * rky0 + mxz.y));
        ey.z = ca4.z * ey.z + cb4.z * ((dHzdx0.z / kx4.z + mzx.z) - (dHxdz0.z * rky0 + mxz.z));
        ey.w = ca4.w * ey.w + cb4.w * ((dHzdx0.w / kx4.w + mzx.w) - (dHxdz0.w * rky0 + mxz.w));

        st4(outEy   + base0, ey);
        st4(outmHzx + base0, mzx);
        st4(outmHxz + base0, mxz);
    }
    // ---- row y1 ----
    {
        float4 mzx = ld4(mHzx + base1);
        mzx.x = bx4.x * mzx.x + ax4.x * dHzdx1.x;
        mzx.y = bx4.y * mzx.y + ax4.y * dHzdx1.y;
        mzx.z = bx4.z * mzx.z + ax4.z * dHzdx1.z;
        mzx.w = bx4.w * mzx.w + ax4.w * dHzdx1.w;

        float4 mxz = ld4(mHxz + base1);
        mxz.x = by1 * mxz.x + ay1 * dHxdz1.x;
        mxz.y = by1 * mxz.y + ay1 * dHxdz1.y;
        mxz.z = by1 * mxz.z + ay1 * dHxdz1.z;
        mxz.w = by1 * mxz.w + ay1 * dHxdz1.w;

        size_t cidx = (size_t)y1 * NX + x4;
        float4 ca4 = ld4(ca + cidx);
        float4 cb4 = ld4(cb + cidx);
        float4 ey  = ld4(Ey + base1);

        ey.x = ca4.x * ey.x + cb4.x * ((dHzdx1.x / kx4.x + mzx.x) - (dHxdz1.x * rky1 + mxz.x));
        ey.y = ca4.y * ey.y + cb4.y * ((dHzdx1.y / kx4.y + mzx.y) - (dHxdz1.y * rky1 + mxz.y));
        ey.z = ca4.z * ey.z + cb4.z * ((dHzdx1.z / kx4.z + mzx.z) - (dHxdz1.z * rky1 + mxz.z));
        ey.w = ca4.w * ey.w + cb4.w * ((dHzdx1.w / kx4.w + mzx.w) - (dHxdz1.w * rky1 + mxz.w));

        st4(outEy   + base1, ey);
        st4(outmHzx + base1, mzx);
        st4(outmHxz + base1, mxz);
    }
}

// ---------------- Kernel 2: update_H (x4 vector, 2 y-rows/thread) ----------------
__global__ void __launch_bounds__(256) upd_H(
    const float* __restrict__ cq,
    const float* __restrict__ EyNew,
    const float* __restrict__ Hx, const float* __restrict__ Hz,
    const float* __restrict__ mEyx, const float* __restrict__ mEyz,
    const float* __restrict__ kyh, const float* __restrict__ ayh,
    const float* __restrict__ byh,
    const float* __restrict__ kxh, const float* __restrict__ axh,
    const float* __restrict__ bxh,
    const float* __restrict__ prdy, const float* __restrict__ prdx,
    float* __restrict__ outHx, float* __restrict__ outHz,
    float* __restrict__ outmEyx, float* __restrict__ outmEyz,
    int NY, int NX)
{
    int x4 = (blockIdx.x * blockDim.x + threadIdx.x) * 4;
    int y0 = (blockIdx.y * blockDim.y + threadIdx.y) * 2;
    int b  = blockIdx.z;
    if (x4 >= NX || y0 >= NY) return;
    int y1 = y0 + 1;

    const float rdx = *prdx;
    const float rdy = *prdy;

    size_t plane = (size_t)NY * NX;
    size_t base0 = (size_t)b * plane + (size_t)y0 * NX + x4;
    size_t base1 = base0 + NX;

    // ---- EyNew rows: y0-1 .. y0+3 (centers e1,e2 shared with x-deriv) ----
    float4 e0 = (y0 >= 1)     ? ld4(EyNew + base0 - (size_t)NX)   : f4zero();
    float4 e1 = ld4(EyNew + base0);
    float4 e2 = ld4(EyNew + base1);
    float4 e3 = (y0 + 2 < NY) ? ld4(EyNew + base0 + 2*(size_t)NX) : f4zero();
    float4 e4 = (y0 + 3 < NY) ? ld4(EyNew + base0 + 3*(size_t)NX) : f4zero();

    // x-halos for both center rows
    float4 p0 = (x4 >= 4)     ? ld4(EyNew + base0 - 4) : f4zero();
    float4 p1 = (x4 >= 4)     ? ld4(EyNew + base1 - 4) : f4zero();
    float4 n0 = (x4 + 4 < NX) ? ld4(EyNew + base0 + 4) : f4zero();
    float4 n1 = (x4 + 4 < NX) ? ld4(EyNew + base1 + 4) : f4zero();

    float4 dEydx0 = xderiv_H(e1, p0, n0, rdx);
    float4 dEydx1 = xderiv_H(e2, p1, n1, rdx);
    // half-grid y-deriv: row y uses y+1, y, y+2, y-1
    float4 dEydz0 = stencil4(e2, e1, e3, e0, rdy);
    float4 dEydz1 = stencil4(e3, e2, e4, e1, rdy);

    // ---- x coefficients (shared) ----
    float4 bxh4 = ld4(bxh + x4);
    float4 axh4 = ld4(axh + x4);
    float4 kxh4 = ld4(kxh + x4);
    float byh0 = byh[y0], ayh0 = ayh[y0], rkyh0 = 1.0f / kyh[y0];
    float byh1 = byh[y1], ayh1 = ayh[y1], rkyh1 = 1.0f / kyh[y1];

    // ---- row y0 ----
    {
        float4 mez = ld4(mEyz + base0);
        mez.x = byh0 * mez.x + ayh0 * dEydz0.x;
        mez.y = byh0 * mez.y + ayh0 * dEydz0.y;
        mez.z = byh0 * mez.z + ayh0 * dEydz0.z;
        mez.w = byh0 * mez.w + ayh0 * dEydz0.w;

        float4 mex = ld4(mEyx + base0);
        mex.x = bxh4.x * mex.x + axh4.x * dEydx0.x;
        mex.y = bxh4.y * mex.y + axh4.y * dEydx0.y;
        mex.z = bxh4.z * mex.z + axh4.z * dEydx0.z;
        mex.w = bxh4.w * mex.w + axh4.w * dEydx0.w;

        size_t cidx = (size_t)y0 * NX + x4;
        float4 cq4 = ld4(cq + cidx);

        float4 hx = ld4(Hx + base0);
        hx.x = hx.x - cq4.x * (dEydz0.x * rkyh0 + mez.x);
        hx.y = hx.y - cq4.y * (dEydz0.y * rkyh0 + mez.y);
        hx.z = hx.z - cq4.z * (dEydz0.z * rkyh0 + mez.z);
        hx.w = hx.w - cq4.w * (dEydz0.w * rkyh0 + mez.w);

        float4 hz = ld4(Hz + base0);
        hz.x = hz.x + cq4.x * (dEydx0.x / kxh4.x + mex.x);
        hz.y = hz.y + cq4.y * (dEydx0.y / kxh4.y + mex.y);
        hz.z = hz.z + cq4.z * (dEydx0.z / kxh4.z + mex.z);
        hz.w = hz.w + cq4.w * (dEydx0.w / kxh4.w + mex.w);

        st4(outHx   + base0, hx);
        st4(outHz   + base0, hz);
        st4(outmEyz + base0, mez);
        st4(outmEyx + base0, mex);
    }
    // ---- row y1 ----
    {
        float4 mez = ld4(mEyz + base1);
        mez.x = byh1 * mez.x + ayh1 * dEydz1.x;
        mez.y = byh1 * mez.y + ayh1 * dEydz1.y;
        mez.z = byh1 * mez.z + ayh1 * dEydz1.z;
        mez.w = byh1 * mez.w + ayh1 * dEydz1.w;

        float4 mex = ld4(mEyx + base1);
        mex.x = bxh4.x * mex.x + axh4.x * dEydx1.x;
        mex.y = bxh4.y * mex.y + axh4.y * dEydx1.y;
        mex.z = bxh4.z * mex.z + axh4.z * dEydx1.z;
        mex.w = bxh4.w * mex.w + axh4.w * dEydx1.w;

        size_t cidx = (size_t)y1 * NX + x4;
        float4 cq4 = ld4(cq + cidx);

        float4 hx = ld4(Hx + base1);
        hx.x = hx.x - cq4.x * (dEydz1.x * rkyh1 + mez.x);
        hx.y = hx.y - cq4.y * (dEydz1.y * rkyh1 + mez.y);
        hx.z = hx.z - cq4.z * (dEydz1.z * rkyh1 + mez.z);
        hx.w = hx.w - cq4.w * (dEydz1.w * rkyh1 + mez.w);

        float4 hz = ld4(Hz + base1);
        hz.x = hz.x + cq4.x * (dEydx1.x / kxh4.x + mex.x);
        hz.y = hz.y + cq4.y * (dEydx1.y / kxh4.y + mex.y);
        hz.z = hz.z + cq4.z * (dEydx1.z / kxh4.z + mex.z);
        hz.w = hz.w + cq4.w * (dEydx1.w / kxh4.w + mex.w);

        st4(outHx   + base1, hx);
        st4(outHz   + base1, hz);
        st4(outmEyz + base1, mez);
        st4(outmEyx + base1, mex);
    }
}

extern "C" void kernel_launch(void* const* d_in, const int* in_sizes, int n_in,
                              void* d_out, int out_size)
{
    const float* ca    = (const float*)d_in[0];
    const float* cb    = (const float*)d_in[1];
    const float* cq    = (const float*)d_in[2];
    const float* Ey    = (const float*)d_in[3];
    const float* Hx    = (const float*)d_in[4];
    const float* Hz    = (const float*)d_in[5];
    const float* mHxz  = (const float*)d_in[6];
    const float* mHzx  = (const float*)d_in[7];
    const float* mEyx  = (const float*)d_in[8];
    const float* mEyz  = (const float*)d_in[9];
    const float* ky    = (const float*)d_in[10];
    const float* kyh   = (const float*)d_in[11];
    const float* ay    = (const float*)d_in[12];
    const float* ayh   = (const float*)d_in[13];
    const float* by    = (const float*)d_in[14];
    const float* byh   = (const float*)d_in[15];
    const float* kx    = (const float*)d_in[16];
    const float* kxh   = (const float*)d_in[17];
    const float* ax    = (const float*)d_in[18];
    const float* axh   = (const float*)d_in[19];
    const float* bx    = (const float*)d_in[20];
    const float* bxh   = (const float*)d_in[21];
    const float* prdy  = (const float*)d_in[22];
    const float* prdx  = (const float*)d_in[23];

    int NY = in_sizes[10];
    int NX = in_sizes[16];
    int B  = in_sizes[3] / (NY * NX);

    size_t plane = (size_t)NY * NX;
    size_t field = (size_t)B * plane;

    float* out = (float*)d_out;
    float* oEy   = out + 0 * field;
    float* oHx   = out + 1 * field;
    float* oHz   = out + 2 * field;
    float* omHxz = out + 3 * field;
    float* omHzx = out + 4 * field;
    float* omEyx = out + 5 * field;
    float* omEyz = out + 6 * field;

    // each thread: 4 x-elements x 2 y-rows
    dim3 block(64, 4, 1);
    int nx4 = NX / 4;                       // 512
    int ny2 = (NY + 1) / 2;                 // 1024
    dim3 grid((nx4 + 63) / 64, (ny2 + 3) / 4, B);

    upd_E<<<grid, block>>>(ca, cb, Ey, Hx, Hz, mHxz, mHzx,
                           ky, ay, by, kx, ax, bx, prdy, prdx,
                           oEy, omHxz, omHzx, NY, NX);

    upd_H<<<grid, block>>>(cq, oEy, Hx, Hz, mEyx, mEyz,
                           kyh, ayh, byh, kxh, axh, bxh, prdy, prdx,
                           oHx, oHz, omEyx, omEyz, NY, NX);
}